// round 14
// baseline (speedup 1.0000x reference)
#include <cuda_runtime.h>
#include <cuda_bf16.h>
#include <cstdint>

#define NROWS 65536
#define ZD    256
#define KCODES 1024
#define BM 64
#define NBLK (NROWS / BM)    // 1024
#define TN 64                // codes per E tile
#define NT (KCODES / TN)     // 16 tiles
#define MARGIN 8e-3f
#define CAND_CAP 1536

#define ZQ_ELEMS ((size_t)NROWS * ZD)
#define IDX_OFF  ZQ_ELEMS
#define LOSS_OFF (ZQ_ELEMS + (size_t)NROWS)

#define ROWB 528                 // 264 bf16 padded row stride (bytes)
#define Z_SM (BM * ROWB)         // 33792
#define E_SM (TN * ROWB)         // 33792
#define SE_OFF(b) (Z_SM + (b) * E_SM)
#define DYN_SMEM (Z_SM + 2 * E_SM)   // 101376

typedef unsigned long long ull;

__device__ float g_enorm[KCODES];
__device__ float g_znorm[NROWS];
__device__ float g_partial[NBLK];
__device__ __nv_bfloat16 g_Ebf16[(size_t)KCODES * ZD];   // 512 KB, row-major

// ---------------- PTX helpers ----------------
__device__ __forceinline__ uint32_t smem_u32(const void* p) {
    uint32_t a;
    asm("{ .reg .u64 t; cvta.to.shared.u64 t, %1; cvt.u32.u64 %0, t; }" : "=r"(a) : "l"(p));
    return a;
}
__device__ __forceinline__ void cp_async16(uint32_t dst, const void* src) {
    asm volatile("cp.async.cg.shared.global [%0], [%1], 16;" :: "r"(dst), "l"(src) : "memory");
}
#define CP_COMMIT() asm volatile("cp.async.commit_group;" ::: "memory")
#define CP_WAIT(N)  asm volatile("cp.async.wait_group %0;" :: "n"(N) : "memory")

__device__ __forceinline__ void ldsm_x4(uint32_t& r0, uint32_t& r1, uint32_t& r2, uint32_t& r3,
                                        uint32_t addr) {
    asm volatile("ldmatrix.sync.aligned.m8n8.x4.shared.b16 {%0,%1,%2,%3}, [%4];"
                 : "=r"(r0), "=r"(r1), "=r"(r2), "=r"(r3) : "r"(addr));
}

// ================= K1: sum-of-squares per row, XLA row-reduce-tree bit-exact ==========
__global__ void sqsum_tree_kernel(const float* __restrict__ src, int nrows, int mode)
{
    int row = blockIdx.x * 8 + (threadIdx.x >> 5);
    if (row >= nrows) return;
    int lane = threadIdx.x & 31;
    const float2* p = (const float2*)(src + (size_t)row * ZD);
    float acc[4];
#pragma unroll
    for (int j = 0; j < 4; j++) {
        float2 v = p[lane + 32 * j];
        acc[j] = __fadd_rn(__fmul_rn(v.x, v.x), __fmul_rn(v.y, v.y));
    }
#pragma unroll
    for (int off = 16; off; off >>= 1)
#pragma unroll
        for (int j = 0; j < 4; j++)
            acc[j] = __fadd_rn(acc[j], __shfl_down_sync(0xffffffffu, acc[j], off));
    if (lane == 0) {
        float s = __fadd_rn(__fadd_rn(acc[0], acc[2]), __fadd_rn(acc[1], acc[3]));
        if (mode == 0) g_znorm[row] = s;
        else           g_enorm[row] = s;
    }
}

// ================= K1b: one-time E fp32 -> bf16 global conversion =================
__global__ void ecvt_kernel(const float* __restrict__ E)
{
    int idx = (blockIdx.x * 256 + threadIdx.x) * 4;
    float4 v = *(const float4*)(E + idx);
    __nv_bfloat162 b0 = __floats2bfloat162_rn(v.x, v.y);
    __nv_bfloat162 b1 = __floats2bfloat162_rn(v.z, v.w);
    uint2 pk;
    pk.x = *reinterpret_cast<unsigned*>(&b0);
    pk.y = *reinterpret_cast<unsigned*>(&b1);
    *(uint2*)(&g_Ebf16[idx]) = pk;
}

// ================= K2: HMMA candidate search + exact fp32 rescore (2 CTA/SM) ==========
__global__ __launch_bounds__(256, 2) void vq_mma(
    const float* __restrict__ Z, const float* __restrict__ E, float* __restrict__ out)
{
    extern __shared__ __align__(16) char dyn[];
    __shared__ float sEn[KCODES];
    __shared__ unsigned sCand[CAND_CAP];
    __shared__ int sCnt;
    __shared__ ull sBest[BM];
    __shared__ float sRed[8];
    __shared__ float sPairMin[4][2][16];   // [mg][ng][row-in-16] per-tile warp mins

    const int tid = threadIdx.x;
    const int wid = tid >> 5, lane = tid & 31;
    const int g = lane >> 2, t = lane & 3;       // quad coords
    const int lr = lane & 7, ls = lane >> 3;     // ldmatrix coords
    const int mg = wid & 3;                      // row group: rows mg*16..+16
    const int ng = wid >> 2;                     // code group: codes ng*32..+32 in tile
    const int row0 = blockIdx.x * BM;

    const uint32_t smBase = smem_u32(dyn);
    const uint32_t smZ = smBase;

    for (int i = tid; i < KCODES; i += 256) sEn[i] = g_enorm[i];
    if (tid < BM) sBest[tid] = ~0ull;
    if (tid == 0) sCnt = 0;

    // ---- Z tile: fp32 -> bf16 padded rows (64 x 256) ----
#pragma unroll
    for (int it = 0; it < 8; it++) {
        int lin = (tid + it * 256) * 8;
        int r = lin >> 8, k = lin & 255;
        float4 v0 = *(const float4*)(Z + (size_t)(row0 + r) * ZD + k);
        float4 v1 = *(const float4*)(Z + (size_t)(row0 + r) * ZD + k + 4);
        __nv_bfloat162 b0 = __floats2bfloat162_rn(v0.x, v0.y);
        __nv_bfloat162 b1 = __floats2bfloat162_rn(v0.z, v0.w);
        __nv_bfloat162 b2 = __floats2bfloat162_rn(v1.x, v1.y);
        __nv_bfloat162 b3 = __floats2bfloat162_rn(v1.z, v1.w);
        uint4 pk;
        pk.x = *reinterpret_cast<unsigned*>(&b0);
        pk.y = *reinterpret_cast<unsigned*>(&b1);
        pk.z = *reinterpret_cast<unsigned*>(&b2);
        pk.w = *reinterpret_cast<unsigned*>(&b3);
        *(uint4*)(dyn + r * ROWB + k * 2) = pk;
    }

    // ---- cp.async E tile 0 into buffer 0 ----
#pragma unroll
    for (int i = 0; i < 8; i++) {
        int ch = tid + i * 256;
        int r = ch >> 5, c16 = ch & 31;
        cp_async16(smBase + SE_OFF(0) + r * ROWB + c16 * 16,
                   (const char*)g_Ebf16 + (size_t)r * 512 + c16 * 16);
    }
    CP_COMMIT();

    // ldmatrix base addresses
    const uint32_t aAddr0 = smZ + (uint32_t)((mg * 16 + (ls & 1) * 8 + lr) * ROWB + (ls >> 1) * 16);
    const uint32_t bOff   = (uint32_t)((ng * 32 + (ls >> 1) * 8 + lr) * ROWB + (ls & 1) * 16);

    float runA = 3.402823466e38f, runB = 3.402823466e38f;  // TRUE per-row prefix mins
    const int rowA = mg * 16 + g, rowB = mg * 16 + g + 8;

    for (int ct = 0; ct < NT; ct++) {
        const int buf = ct & 1;
        if (ct < NT - 1) {
#pragma unroll
            for (int i = 0; i < 8; i++) {
                int ch = tid + i * 256;
                int r = ch >> 5, c16 = ch & 31;
                cp_async16(smBase + SE_OFF(buf ^ 1) + r * ROWB + c16 * 16,
                           (const char*)g_Ebf16 + (size_t)(ct + 1) * TN * 512
                                                + (size_t)r * 512 + c16 * 16);
            }
            CP_COMMIT();
            CP_WAIT(1);
        } else {
            CP_WAIT(0);
        }
        __syncthreads();

        const uint32_t smE = smBase + SE_OFF(buf);
        float dacc[4][4];
#pragma unroll
        for (int nt = 0; nt < 4; nt++) {
            dacc[nt][0] = 0.f; dacc[nt][1] = 0.f; dacc[nt][2] = 0.f; dacc[nt][3] = 0.f;
        }
#pragma unroll
        for (int ks = 0; ks < 16; ks++) {
            uint32_t a0, a1, a2, a3;
            ldsm_x4(a0, a1, a2, a3, aAddr0 + ks * 32);
#pragma unroll
            for (int p = 0; p < 2; p++) {
                uint32_t b0, b1, b2, b3;
                ldsm_x4(b0, b1, b2, b3, smE + bOff + p * (16 * ROWB) + ks * 32);
                asm volatile(
                    "mma.sync.aligned.m16n8k16.row.col.f32.bf16.bf16.f32 "
                    "{%0,%1,%2,%3}, {%4,%5,%6,%7}, {%8,%9}, {%0,%1,%2,%3};"
                    : "+f"(dacc[2 * p][0]), "+f"(dacc[2 * p][1]),
                      "+f"(dacc[2 * p][2]), "+f"(dacc[2 * p][3])
                    : "r"(a0), "r"(a1), "r"(a2), "r"(a3), "r"(b0), "r"(b1));
                asm volatile(
                    "mma.sync.aligned.m16n8k16.row.col.f32.bf16.bf16.f32 "
                    "{%0,%1,%2,%3}, {%4,%5,%6,%7}, {%8,%9}, {%0,%1,%2,%3};"
                    : "+f"(dacc[2 * p + 1][0]), "+f"(dacc[2 * p + 1][1]),
                      "+f"(dacc[2 * p + 1][2]), "+f"(dacc[2 * p + 1][3])
                    : "r"(a0), "r"(a1), "r"(a2), "r"(a3), "r"(b2), "r"(b3));
            }
        }

        // ---- scores + per-warp tile row-mins ----
        float v[4][4];
        float tA = 3.402823466e38f, tB = 3.402823466e38f;
#pragma unroll
        for (int nt = 0; nt < 4; nt++) {
            int c0 = ct * TN + ng * 32 + nt * 8 + 2 * t;
            float e0 = sEn[c0], e1 = sEn[c0 + 1];
            v[nt][0] = __fmaf_rn(-2.0f, dacc[nt][0], e0);
            v[nt][1] = __fmaf_rn(-2.0f, dacc[nt][1], e1);
            v[nt][2] = __fmaf_rn(-2.0f, dacc[nt][2], e0);
            v[nt][3] = __fmaf_rn(-2.0f, dacc[nt][3], e1);
            tA = fminf(tA, fminf(v[nt][0], v[nt][1]));
            tB = fminf(tB, fminf(v[nt][2], v[nt][3]));
        }
        tA = fminf(tA, __shfl_xor_sync(0xffffffffu, tA, 1));
        tA = fminf(tA, __shfl_xor_sync(0xffffffffu, tA, 2));
        tB = fminf(tB, __shfl_xor_sync(0xffffffffu, tB, 1));
        tB = fminf(tB, __shfl_xor_sync(0xffffffffu, tB, 2));
        if (t == 0) {                      // publish this warp's 16 tile row-mins
            sPairMin[mg][ng][g]     = tA;
            sPairMin[mg][ng][g + 8] = tB;
        }
        __syncthreads();                   // both ng halves visible
        // combine across the code-split warp pair -> TRUE per-row tile min
        float cA = fminf(sPairMin[mg][0][g],     sPairMin[mg][1][g]);
        float cB = fminf(sPairMin[mg][0][g + 8], sPairMin[mg][1][g + 8]);
        runA = fminf(runA, cA);
        runB = fminf(runB, cB);
        float limA = runA + MARGIN;
        float limB = runB + MARGIN;
#pragma unroll
        for (int nt = 0; nt < 4; nt++) {
            int c0 = ct * TN + ng * 32 + nt * 8 + 2 * t;
            if (v[nt][0] < limA) {
                int s = atomicAdd(&sCnt, 1);
                if (s < CAND_CAP) sCand[s] = (unsigned)((rowA << 10) | c0);
            }
            if (v[nt][1] < limA) {
                int s = atomicAdd(&sCnt, 1);
                if (s < CAND_CAP) sCand[s] = (unsigned)((rowA << 10) | (c0 + 1));
            }
            if (v[nt][2] < limB) {
                int s = atomicAdd(&sCnt, 1);
                if (s < CAND_CAP) sCand[s] = (unsigned)((rowB << 10) | c0);
            }
            if (v[nt][3] < limB) {
                int s = atomicAdd(&sCnt, 1);
                if (s < CAND_CAP) sCand[s] = (unsigned)((rowB << 10) | (c0 + 1));
            }
        }
        __syncthreads();                   // pushes + sPairMin reads done before reuse
    }

    // ================= exact fp32 rescore (reference op order) =================
    {
        int cnt = sCnt;
        if (cnt > CAND_CAP) cnt = CAND_CAP;
        for (int idx = tid; idx < cnt; idx += 256) {
            unsigned e = sCand[idx];
            int i = e >> 10;
            int c = e & 1023;
            int r = row0 + i;
            const float4* zp = (const float4*)(Z + (size_t)r * ZD);
            const float4* ep = (const float4*)(E + (size_t)c * ZD);
            float acc = 0.0f;     // serial k-ascending single-accumulator chain
#pragma unroll 8
            for (int k = 0; k < 64; k++) {
                float4 a = zp[k];
                float4 b = ep[k];
                acc = __fmaf_rn(a.x, b.x, acc);
                acc = __fmaf_rn(a.y, b.y, acc);
                acc = __fmaf_rn(a.z, b.z, acc);
                acc = __fmaf_rn(a.w, b.w, acc);
            }
            float s = __fmaf_rn(-2.0f, acc, __fadd_rn(g_znorm[r], sEn[c]));
            ull key = ((ull)__float_as_uint(s) << 32) | (unsigned)c;   // s > 0
            atomicMin(&sBest[i], key);   // min score, tie -> min index
        }
    }
    __syncthreads();

    // ================= epilogue: gather z_q; z_q_st = fl(z + fl(z_q - z)); loss ========
    const float* Ablk = Z + (size_t)row0 * ZD;
    float lsum = 0.0f;
#pragma unroll
    for (int it = 0; it < 16; it++) {
        int e2 = tid + it * 256;
        int m = e2 >> 6;
        int c4 = (e2 & 63) * 4;
        int idx = (int)(unsigned)(sBest[m] & 0xffffffffull);
        float4 q  = *(const float4*)(E + (size_t)idx * ZD + c4);
        float4 z4 = *(const float4*)(Ablk + (size_t)m * ZD + c4);
        float d0 = __fadd_rn(q.x, -z4.x), d1 = __fadd_rn(q.y, -z4.y);
        float d2 = __fadd_rn(q.z, -z4.z), d3 = __fadd_rn(q.w, -z4.w);
        float4 o;
        o.x = __fadd_rn(z4.x, d0); o.y = __fadd_rn(z4.y, d1);
        o.z = __fadd_rn(z4.z, d2); o.w = __fadd_rn(z4.w, d3);
        lsum += d0 * d0 + d1 * d1 + d2 * d2 + d3 * d3;
        *(float4*)(out + (size_t)(row0 + m) * ZD + c4) = o;
    }
    if (tid < BM) out[IDX_OFF + row0 + tid] = (float)(unsigned)(sBest[tid] & 0xffffffffull);

#pragma unroll
    for (int o = 16; o; o >>= 1) lsum += __shfl_xor_sync(0xffffffffu, lsum, o);
    if ((tid & 31) == 0) sRed[tid >> 5] = lsum;
    __syncthreads();
    if (tid < 8) {
        float x = sRed[tid];
        x += __shfl_xor_sync(0xffu, x, 4);
        x += __shfl_xor_sync(0xffu, x, 2);
        x += __shfl_xor_sync(0xffu, x, 1);
        if (tid == 0) g_partial[blockIdx.x] = x;
    }
}

// ================= K3: deterministic final loss reduction (1024 partials) =============
__global__ void finalize_kernel(float* __restrict__ out) {
    __shared__ float s[32];
    int t = threadIdx.x;   // 1024 threads
    float v = g_partial[t];
#pragma unroll
    for (int o = 16; o; o >>= 1) v += __shfl_xor_sync(0xffffffffu, v, o);
    if ((t & 31) == 0) s[t >> 5] = v;
    __syncthreads();
    if (t < 32) {
        float x = s[t];
#pragma unroll
        for (int o = 16; o; o >>= 1) x += __shfl_xor_sync(0xffffffffu, x, o);
        if (t == 0) {
            float mean = x / (float)((size_t)NROWS * ZD);
            out[LOSS_OFF] = mean + 0.25f * mean;   // (1 + BETA) * mean((z_q - z)^2)
        }
    }
}

extern "C" void kernel_launch(void* const* d_in, const int* in_sizes, int n_in,
                              void* d_out, int out_size) {
    const float* Z = (const float*)d_in[0];
    const float* E = (const float*)d_in[1];
    if (n_in >= 2 && in_sizes[0] < in_sizes[1]) { const float* t = Z; Z = E; E = t; }
    float* out = (float*)d_out;

    cudaFuncSetAttribute(vq_mma, cudaFuncAttributeMaxDynamicSharedMemorySize, DYN_SMEM);

    sqsum_tree_kernel<<<(NROWS + 7) / 8, 256>>>(Z, NROWS, 0);   // -> g_znorm
    sqsum_tree_kernel<<<(KCODES + 7) / 8, 256>>>(E, KCODES, 1); // -> g_enorm
    ecvt_kernel<<<KCODES * ZD / 1024, 256>>>(E);                // -> g_Ebf16
    vq_mma<<<NBLK, 256, DYN_SMEM>>>(Z, E, out);
    finalize_kernel<<<1, 1024>>>(out);
}

// round 15
// speedup vs baseline: 1.0467x; 1.0467x over previous
#include <cuda_runtime.h>
#include <cuda_bf16.h>
#include <cstdint>

#define NROWS 65536
#define ZD    256
#define KCODES 1024
#define BM 64
#define NBLK (NROWS / BM)    // 1024
#define TN 64                // codes per E tile
#define NT (KCODES / TN)     // 16 tiles
#define MARGIN 8e-3f
#define CAND_CAP 1536

#define ZQ_ELEMS ((size_t)NROWS * ZD)
#define IDX_OFF  ZQ_ELEMS
#define LOSS_OFF (ZQ_ELEMS + (size_t)NROWS)

#define ROWB 528                 // 264 bf16 padded row stride (bytes)
#define Z_SM (BM * ROWB)         // 33792
#define E_SM (TN * ROWB)         // 33792
#define SE_OFF(b) (Z_SM + (b) * E_SM)
#define DYN_SMEM (Z_SM + 2 * E_SM)   // 101376

typedef unsigned long long ull;

__device__ float g_enorm[KCODES];
__device__ float g_znorm[NROWS];
__device__ float g_partial[NBLK];
__device__ __nv_bfloat16 g_Ebf16[(size_t)KCODES * ZD];   // 512 KB, row-major

// ---------------- PTX helpers ----------------
__device__ __forceinline__ uint32_t smem_u32(const void* p) {
    uint32_t a;
    asm("{ .reg .u64 t; cvta.to.shared.u64 t, %1; cvt.u32.u64 %0, t; }" : "=r"(a) : "l"(p));
    return a;
}
__device__ __forceinline__ void cp_async16(uint32_t dst, const void* src) {
    asm volatile("cp.async.cg.shared.global [%0], [%1], 16;" :: "r"(dst), "l"(src) : "memory");
}
#define CP_COMMIT() asm volatile("cp.async.commit_group;" ::: "memory")
#define CP_WAIT(N)  asm volatile("cp.async.wait_group %0;" :: "n"(N) : "memory")

__device__ __forceinline__ void ldsm_x4(uint32_t& r0, uint32_t& r1, uint32_t& r2, uint32_t& r3,
                                        uint32_t addr) {
    asm volatile("ldmatrix.sync.aligned.m8n8.x4.shared.b16 {%0,%1,%2,%3}, [%4];"
                 : "=r"(r0), "=r"(r1), "=r"(r2), "=r"(r3) : "r"(addr));
}

// ================= K1: sum-of-squares per row, XLA row-reduce-tree bit-exact ==========
__global__ void sqsum_tree_kernel(const float* __restrict__ src, int nrows, int mode)
{
    int row = blockIdx.x * 8 + (threadIdx.x >> 5);
    if (row >= nrows) return;
    int lane = threadIdx.x & 31;
    const float2* p = (const float2*)(src + (size_t)row * ZD);
    float acc[4];
#pragma unroll
    for (int j = 0; j < 4; j++) {
        float2 v = p[lane + 32 * j];
        acc[j] = __fadd_rn(__fmul_rn(v.x, v.x), __fmul_rn(v.y, v.y));
    }
#pragma unroll
    for (int off = 16; off; off >>= 1)
#pragma unroll
        for (int j = 0; j < 4; j++)
            acc[j] = __fadd_rn(acc[j], __shfl_down_sync(0xffffffffu, acc[j], off));
    if (lane == 0) {
        float s = __fadd_rn(__fadd_rn(acc[0], acc[2]), __fadd_rn(acc[1], acc[3]));
        if (mode == 0) g_znorm[row] = s;
        else           g_enorm[row] = s;
    }
}

// ================= K1b: one-time E fp32 -> bf16 global conversion =================
__global__ void ecvt_kernel(const float* __restrict__ E)
{
    int idx = (blockIdx.x * 256 + threadIdx.x) * 4;
    float4 v = *(const float4*)(E + idx);
    __nv_bfloat162 b0 = __floats2bfloat162_rn(v.x, v.y);
    __nv_bfloat162 b1 = __floats2bfloat162_rn(v.z, v.w);
    uint2 pk;
    pk.x = *reinterpret_cast<unsigned*>(&b0);
    pk.y = *reinterpret_cast<unsigned*>(&b1);
    *(uint2*)(&g_Ebf16[idx]) = pk;
}

// ================= K2: HMMA candidate search + exact fp32 rescore =====================
// v15: persistent A fragments in registers (loaded once, reused across all 16 E tiles)
// + B-fragment register double-buffer (prefetch ks+1 before ks's MMAs). LDSM per
// warp-tile drops 48 -> 32 and leaves the dependency critical path.
__global__ __launch_bounds__(256, 2) void vq_mma(
    const float* __restrict__ Z, const float* __restrict__ E, float* __restrict__ out)
{
    extern __shared__ __align__(16) char dyn[];
    __shared__ float sEn[KCODES];
    __shared__ unsigned sCand[CAND_CAP];
    __shared__ int sCnt;
    __shared__ ull sBest[BM];
    __shared__ float sRed[8];
    __shared__ float sPairMin[4][2][16];   // [mg][ng][row-in-16] per-tile warp mins

    const int tid = threadIdx.x;
    const int wid = tid >> 5, lane = tid & 31;
    const int g = lane >> 2, t = lane & 3;       // quad coords
    const int lr = lane & 7, ls = lane >> 3;     // ldmatrix coords
    const int mg = wid & 3;                      // row group: rows mg*16..+16
    const int ng = wid >> 2;                     // code group: codes ng*32..+32 in tile
    const int row0 = blockIdx.x * BM;

    const uint32_t smBase = smem_u32(dyn);
    const uint32_t smZ = smBase;

    for (int i = tid; i < KCODES; i += 256) sEn[i] = g_enorm[i];
    if (tid < BM) sBest[tid] = ~0ull;
    if (tid == 0) sCnt = 0;

    // ---- Z tile: fp32 -> bf16 padded rows (64 x 256) ----
#pragma unroll
    for (int it = 0; it < 8; it++) {
        int lin = (tid + it * 256) * 8;
        int r = lin >> 8, k = lin & 255;
        float4 v0 = *(const float4*)(Z + (size_t)(row0 + r) * ZD + k);
        float4 v1 = *(const float4*)(Z + (size_t)(row0 + r) * ZD + k + 4);
        __nv_bfloat162 b0 = __floats2bfloat162_rn(v0.x, v0.y);
        __nv_bfloat162 b1 = __floats2bfloat162_rn(v0.z, v0.w);
        __nv_bfloat162 b2 = __floats2bfloat162_rn(v1.x, v1.y);
        __nv_bfloat162 b3 = __floats2bfloat162_rn(v1.z, v1.w);
        uint4 pk;
        pk.x = *reinterpret_cast<unsigned*>(&b0);
        pk.y = *reinterpret_cast<unsigned*>(&b1);
        pk.z = *reinterpret_cast<unsigned*>(&b2);
        pk.w = *reinterpret_cast<unsigned*>(&b3);
        *(uint4*)(dyn + r * ROWB + k * 2) = pk;
    }

    // ---- cp.async E tile 0 into buffer 0 ----
#pragma unroll
    for (int i = 0; i < 8; i++) {
        int ch = tid + i * 256;
        int r = ch >> 5, c16 = ch & 31;
        cp_async16(smBase + SE_OFF(0) + r * ROWB + c16 * 16,
                   (const char*)g_Ebf16 + (size_t)r * 512 + c16 * 16);
    }
    CP_COMMIT();

    // ldmatrix base addresses
    const uint32_t aAddr0 = smZ + (uint32_t)((mg * 16 + (ls & 1) * 8 + lr) * ROWB + (ls >> 1) * 16);
    const uint32_t bOff   = (uint32_t)((ng * 32 + (ls >> 1) * 8 + lr) * ROWB + (ls & 1) * 16);

    // ---- persistent A fragments: full K=256 for this warp's 16 rows (64 regs) ----
    __syncthreads();                       // all Z stores visible
    uint32_t afr[16][4];
#pragma unroll
    for (int ks = 0; ks < 16; ks++)
        ldsm_x4(afr[ks][0], afr[ks][1], afr[ks][2], afr[ks][3], aAddr0 + ks * 32);

    float runA = 3.402823466e38f, runB = 3.402823466e38f;  // TRUE per-row prefix mins
    const int rowA = mg * 16 + g, rowB = mg * 16 + g + 8;

    for (int ct = 0; ct < NT; ct++) {
        const int buf = ct & 1;
        if (ct < NT - 1) {
#pragma unroll
            for (int i = 0; i < 8; i++) {
                int ch = tid + i * 256;
                int r = ch >> 5, c16 = ch & 31;
                cp_async16(smBase + SE_OFF(buf ^ 1) + r * ROWB + c16 * 16,
                           (const char*)g_Ebf16 + (size_t)(ct + 1) * TN * 512
                                                + (size_t)r * 512 + c16 * 16);
            }
            CP_COMMIT();
            CP_WAIT(1);
        } else {
            CP_WAIT(0);
        }
        __syncthreads();

        const uint32_t smE = smBase + SE_OFF(buf);
        float dacc[4][4];
#pragma unroll
        for (int nt = 0; nt < 4; nt++) {
            dacc[nt][0] = 0.f; dacc[nt][1] = 0.f; dacc[nt][2] = 0.f; dacc[nt][3] = 0.f;
        }

        // ---- B register double-buffer mainloop (A never touches smem) ----
        uint32_t bq[2][8];
        ldsm_x4(bq[0][0], bq[0][1], bq[0][2], bq[0][3], smE + bOff);
        ldsm_x4(bq[0][4], bq[0][5], bq[0][6], bq[0][7], smE + bOff + 16 * ROWB);
#pragma unroll
        for (int ks = 0; ks < 16; ks++) {
            const int cur = ks & 1, nxt = cur ^ 1;
            if (ks < 15) {
                ldsm_x4(bq[nxt][0], bq[nxt][1], bq[nxt][2], bq[nxt][3],
                        smE + bOff + (ks + 1) * 32);
                ldsm_x4(bq[nxt][4], bq[nxt][5], bq[nxt][6], bq[nxt][7],
                        smE + bOff + 16 * ROWB + (ks + 1) * 32);
            }
#pragma unroll
            for (int p = 0; p < 2; p++) {
                asm volatile(
                    "mma.sync.aligned.m16n8k16.row.col.f32.bf16.bf16.f32 "
                    "{%0,%1,%2,%3}, {%4,%5,%6,%7}, {%8,%9}, {%0,%1,%2,%3};"
                    : "+f"(dacc[2 * p][0]), "+f"(dacc[2 * p][1]),
                      "+f"(dacc[2 * p][2]), "+f"(dacc[2 * p][3])
                    : "r"(afr[ks][0]), "r"(afr[ks][1]), "r"(afr[ks][2]), "r"(afr[ks][3]),
                      "r"(bq[cur][4 * p + 0]), "r"(bq[cur][4 * p + 1]));
                asm volatile(
                    "mma.sync.aligned.m16n8k16.row.col.f32.bf16.bf16.f32 "
                    "{%0,%1,%2,%3}, {%4,%5,%6,%7}, {%8,%9}, {%0,%1,%2,%3};"
                    : "+f"(dacc[2 * p + 1][0]), "+f"(dacc[2 * p + 1][1]),
                      "+f"(dacc[2 * p + 1][2]), "+f"(dacc[2 * p + 1][3])
                    : "r"(afr[ks][0]), "r"(afr[ks][1]), "r"(afr[ks][2]), "r"(afr[ks][3]),
                      "r"(bq[cur][4 * p + 2]), "r"(bq[cur][4 * p + 3]));
            }
        }

        // ---- scores + per-warp tile row-mins ----
        float v[4][4];
        float tA = 3.402823466e38f, tB = 3.402823466e38f;
#pragma unroll
        for (int nt = 0; nt < 4; nt++) {
            int c0 = ct * TN + ng * 32 + nt * 8 + 2 * t;
            float e0 = sEn[c0], e1 = sEn[c0 + 1];
            v[nt][0] = __fmaf_rn(-2.0f, dacc[nt][0], e0);
            v[nt][1] = __fmaf_rn(-2.0f, dacc[nt][1], e1);
            v[nt][2] = __fmaf_rn(-2.0f, dacc[nt][2], e0);
            v[nt][3] = __fmaf_rn(-2.0f, dacc[nt][3], e1);
            tA = fminf(tA, fminf(v[nt][0], v[nt][1]));
            tB = fminf(tB, fminf(v[nt][2], v[nt][3]));
        }
        tA = fminf(tA, __shfl_xor_sync(0xffffffffu, tA, 1));
        tA = fminf(tA, __shfl_xor_sync(0xffffffffu, tA, 2));
        tB = fminf(tB, __shfl_xor_sync(0xffffffffu, tB, 1));
        tB = fminf(tB, __shfl_xor_sync(0xffffffffu, tB, 2));
        if (t == 0) {                      // publish this warp's 16 tile row-mins
            sPairMin[mg][ng][g]     = tA;
            sPairMin[mg][ng][g + 8] = tB;
        }
        __syncthreads();                   // both ng halves visible
        float cA = fminf(sPairMin[mg][0][g],     sPairMin[mg][1][g]);
        float cB = fminf(sPairMin[mg][0][g + 8], sPairMin[mg][1][g + 8]);
        runA = fminf(runA, cA);
        runB = fminf(runB, cB);
        float limA = runA + MARGIN;
        float limB = runB + MARGIN;
#pragma unroll
        for (int nt = 0; nt < 4; nt++) {
            int c0 = ct * TN + ng * 32 + nt * 8 + 2 * t;
            if (v[nt][0] < limA) {
                int s = atomicAdd(&sCnt, 1);
                if (s < CAND_CAP) sCand[s] = (unsigned)((rowA << 10) | c0);
            }
            if (v[nt][1] < limA) {
                int s = atomicAdd(&sCnt, 1);
                if (s < CAND_CAP) sCand[s] = (unsigned)((rowA << 10) | (c0 + 1));
            }
            if (v[nt][2] < limB) {
                int s = atomicAdd(&sCnt, 1);
                if (s < CAND_CAP) sCand[s] = (unsigned)((rowB << 10) | c0);
            }
            if (v[nt][3] < limB) {
                int s = atomicAdd(&sCnt, 1);
                if (s < CAND_CAP) sCand[s] = (unsigned)((rowB << 10) | (c0 + 1));
            }
        }
        __syncthreads();                   // pushes + sPairMin reads done before reuse
    }

    // ================= exact fp32 rescore (reference op order) =================
    {
        int cnt = sCnt;
        if (cnt > CAND_CAP) cnt = CAND_CAP;
        for (int idx = tid; idx < cnt; idx += 256) {
            unsigned e = sCand[idx];
            int i = e >> 10;
            int c = e & 1023;
            int r = row0 + i;
            const float4* zp = (const float4*)(Z + (size_t)r * ZD);
            const float4* ep = (const float4*)(E + (size_t)c * ZD);
            float acc = 0.0f;     // serial k-ascending single-accumulator chain
#pragma unroll 8
            for (int k = 0; k < 64; k++) {
                float4 a = zp[k];
                float4 b = ep[k];
                acc = __fmaf_rn(a.x, b.x, acc);
                acc = __fmaf_rn(a.y, b.y, acc);
                acc = __fmaf_rn(a.z, b.z, acc);
                acc = __fmaf_rn(a.w, b.w, acc);
            }
            float s = __fmaf_rn(-2.0f, acc, __fadd_rn(g_znorm[r], sEn[c]));
            ull key = ((ull)__float_as_uint(s) << 32) | (unsigned)c;   // s > 0
            atomicMin(&sBest[i], key);   // min score, tie -> min index
        }
    }
    __syncthreads();

    // ================= epilogue: gather z_q; z_q_st = fl(z + fl(z_q - z)); loss ========
    const float* Ablk = Z + (size_t)row0 * ZD;
    float lsum = 0.0f;
#pragma unroll
    for (int it = 0; it < 16; it++) {
        int e2 = tid + it * 256;
        int m = e2 >> 6;
        int c4 = (e2 & 63) * 4;
        int idx = (int)(unsigned)(sBest[m] & 0xffffffffull);
        float4 q  = *(const float4*)(E + (size_t)idx * ZD + c4);
        float4 z4 = *(const float4*)(Ablk + (size_t)m * ZD + c4);
        float d0 = __fadd_rn(q.x, -z4.x), d1 = __fadd_rn(q.y, -z4.y);
        float d2 = __fadd_rn(q.z, -z4.z), d3 = __fadd_rn(q.w, -z4.w);
        float4 o;
        o.x = __fadd_rn(z4.x, d0); o.y = __fadd_rn(z4.y, d1);
        o.z = __fadd_rn(z4.z, d2); o.w = __fadd_rn(z4.w, d3);
        lsum += d0 * d0 + d1 * d1 + d2 * d2 + d3 * d3;
        *(float4*)(out + (size_t)(row0 + m) * ZD + c4) = o;
    }
    if (tid < BM) out[IDX_OFF + row0 + tid] = (float)(unsigned)(sBest[tid] & 0xffffffffull);

#pragma unroll
    for (int o = 16; o; o >>= 1) lsum += __shfl_xor_sync(0xffffffffu, lsum, o);
    if ((tid & 31) == 0) sRed[tid >> 5] = lsum;
    __syncthreads();
    if (tid < 8) {
        float x = sRed[tid];
        x += __shfl_xor_sync(0xffu, x, 4);
        x += __shfl_xor_sync(0xffu, x, 2);
        x += __shfl_xor_sync(0xffu, x, 1);
        if (tid == 0) g_partial[blockIdx.x] = x;
    }
}

// ================= K3: deterministic final loss reduction (1024 partials) =============
__global__ void finalize_kernel(float* __restrict__ out) {
    __shared__ float s[32];
    int t = threadIdx.x;   // 1024 threads
    float v = g_partial[t];
#pragma unroll
    for (int o = 16; o; o >>= 1) v += __shfl_xor_sync(0xffffffffu, v, o);
    if ((t & 31) == 0) s[t >> 5] = v;
    __syncthreads();
    if (t < 32) {
        float x = s[t];
#pragma unroll
        for (int o = 16; o; o >>= 1) x += __shfl_xor_sync(0xffffffffu, x, o);
        if (t == 0) {
            float mean = x / (float)((size_t)NROWS * ZD);
            out[LOSS_OFF] = mean + 0.25f * mean;   // (1 + BETA) * mean((z_q - z)^2)
        }
    }
}

extern "C" void kernel_launch(void* const* d_in, const int* in_sizes, int n_in,
                              void* d_out, int out_size) {
    const float* Z = (const float*)d_in[0];
    const float* E = (const float*)d_in[1];
    if (n_in >= 2 && in_sizes[0] < in_sizes[1]) { const float* t = Z; Z = E; E = t; }
    float* out = (float*)d_out;

    cudaFuncSetAttribute(vq_mma, cudaFuncAttributeMaxDynamicSharedMemorySize, DYN_SMEM);

    sqsum_tree_kernel<<<(NROWS + 7) / 8, 256>>>(Z, NROWS, 0);   // -> g_znorm
    sqsum_tree_kernel<<<(KCODES + 7) / 8, 256>>>(E, KCODES, 1); // -> g_enorm
    ecvt_kernel<<<KCODES * ZD / 1024, 256>>>(E);                // -> g_Ebf16
    vq_mma<<<NBLK, 256, DYN_SMEM>>>(Z, E, out);
    finalize_kernel<<<1, 1024>>>(out);
}